// round 6
// baseline (speedup 1.0000x reference)
#include <cuda_runtime.h>
#include <cuda_fp16.h>

#define N_NODES 50000
#define N_EDGES 800000
#define IN_C    16
#define OUT_C   16
#define EDGE_F  8

// y table in fp16: per node 9 blocks (8 edge-feature + 1 bias) x 16 outputs,
// = 18 uint4, PADDED to 24 uint4 (384 B = 3 cache lines, 128B-aligned).
// slot j = f*2 + h  (f = feature block, h = output half, uint4 units)
#define YSTRIDE 24

__device__ __align__(128) uint4 g_yh[N_NODES * YSTRIDE];   // 19.2 MB

// ---------------------------------------------------------------------------
// Kernel A: per-node precompute. Thread = (node, output-half h).
//   - 9 fp16 y-blocks  -> g_yh
//   - root-term half   -> out[n][h*8 .. h*8+7]  (fused, reuses x registers)
//   - echo streaming of edge_index / edge_attr
// ---------------------------------------------------------------------------
__global__ void node_kernel(const float* __restrict__ x,
                            const int*   __restrict__ ei,
                            const float* __restrict__ ea,
                            const float* __restrict__ w_nn,
                            const float* __restrict__ b_nn,
                            const float* __restrict__ root,
                            const float* __restrict__ bias,
                            float* __restrict__ out,
                            int echo)
{
    __shared__ float Wsh[9 * 256];      // [f][i*16+o], f==8 holds b_nn
    __shared__ float Rsh[256 + 16];     // root [i][o] + bias[o]

    for (int t = threadIdx.x; t < 2048; t += blockDim.x) Wsh[t] = w_nn[t];
    for (int t = threadIdx.x; t < 256;  t += blockDim.x) Wsh[2048 + t] = b_nn[t];
    for (int t = threadIdx.x; t < 256;  t += blockDim.x) Rsh[t] = root[t];
    for (int t = threadIdx.x; t < 16;   t += blockDim.x) Rsh[256 + t] = bias[t];
    __syncthreads();

    const int gsz  = gridDim.x * blockDim.x;
    const int tid0 = blockIdx.x * blockDim.x + threadIdx.x;

    for (int t = tid0; t < N_NODES * 2; t += gsz) {
        int n = t >> 1;
        int h = t & 1;                 // outputs h*8 .. h*8+7

        const float4* xr = (const float4*)(x + n * IN_C);
        float xv[16];
        #pragma unroll
        for (int ii = 0; ii < 4; ii++) {
            float4 xx = xr[ii];
            xv[4*ii+0] = xx.x; xv[4*ii+1] = xx.y; xv[4*ii+2] = xx.z; xv[4*ii+3] = xx.w;
        }

        // ---- 9 y-blocks (8 edge-feature + bias block) ----
        #pragma unroll
        for (int f = 0; f < 9; f++) {
            const float* wb = &Wsh[f * 256 + h * 8];
            float acc[8];
            #pragma unroll
            for (int o = 0; o < 8; o++) acc[o] = 0.f;
            #pragma unroll
            for (int i = 0; i < 16; i++) {
                float xi = xv[i];
                #pragma unroll
                for (int o = 0; o < 8; o++) acc[o] += xi * wb[i * 16 + o];
            }
            __half2 hv[4];
            #pragma unroll
            for (int j = 0; j < 4; j++)
                hv[j] = __floats2half2_rn(acc[2*j], acc[2*j+1]);
            g_yh[n * YSTRIDE + f * 2 + h] = *(const uint4*)hv;
        }

        // ---- fused root-term half: out[n][h*8+o] = bias + x[n] @ root ----
        {
            float racc[8];
            #pragma unroll
            for (int o = 0; o < 8; o++) racc[o] = Rsh[256 + h * 8 + o];
            #pragma unroll
            for (int i = 0; i < 16; i++) {
                float xi = xv[i];
                #pragma unroll
                for (int o = 0; o < 8; o++) racc[o] += xi * Rsh[i * 16 + h * 8 + o];
            }
            float4* od = (float4*)(out + n * OUT_C + h * 8);
            od[0] = make_float4(racc[0], racc[1], racc[2], racc[3]);
            od[1] = make_float4(racc[4], racc[5], racc[6], racc[7]);
        }
    }

    // ---- echoes (streaming, DRAM-bound) ----
    if (echo & 1) {
        for (int t = tid0; t < 2 * N_EDGES; t += gsz)
            out[N_NODES * OUT_C + t] = (float)ei[t];
    }
    if (echo & 2) {
        float4*       dst4 = (float4*)(out + N_NODES * OUT_C + 2 * N_EDGES);
        const float4* src4 = (const float4*)ea;
        for (int t = tid0; t < N_EDGES * 2; t += gsz)
            dst4[t] = src4[t];
    }
}

// ---------------------------------------------------------------------------
// Kernel B: 8 lanes per edge (4 edges/warp), split accumulators.
//   Lane sub loads slots {sub, sub+8} (+bias slot 16+sub for sub<2):
//   gather = 3 LDG.128 instructions covering the 3 cache lines of the row
//   -> 3 line-wavefronts/edge. Lane accumulates ONLY its 2(3) blocks
//   (h = sub&1, f = sub>>1 and 4+(sub>>1)). Two shfl_xor rounds combine the
//   4 lanes of each h-parity. Then ALL 8 lanes issue one red.v2 covering the
//   64 B dst row in a single instruction -> 1 scatter wavefront/edge.
// ---------------------------------------------------------------------------
__global__ void edge_kernel(const int*   __restrict__ ei,
                            const float* __restrict__ ea,
                            float* __restrict__ out)
{
    const int g   = blockIdx.x * blockDim.x + threadIdx.x;
    const int e   = g >> 3;                 // edge id (grid exact: 800k*8 threads)
    const int sub = g & 7;
    const int s2  = sub >> 1;               // 0..3

    const int src = __ldg(&ei[e]);
    const int dst = __ldg(&ei[N_EDGES + e]);

    // this lane's two coefficients: f = s2 and f = 4+s2
    const float c0 = __ldg(&ea[e * EDGE_F + s2]);
    const float c1 = __ldg(&ea[e * EDGE_F + 4 + s2]);

    const uint4* yrow = g_yh + src * YSTRIDE;
    const uint4 v0 = yrow[sub];        // line 0: (f = s2,    h = sub&1)
    const uint4 v1 = yrow[8 + sub];    // line 1: (f = 4+s2,  h = sub&1)

    float acc[8];
    if (sub < 2) {                     // line 2: bias block (f=8, h=sub), coef 1
        const uint4 vb = yrow[16 + sub];
        const __half2* hv = (const __half2*)&vb;
        #pragma unroll
        for (int j = 0; j < 4; j++) {
            float2 p = __half22float2(hv[j]);
            acc[2*j] = p.x; acc[2*j+1] = p.y;
        }
    } else {
        #pragma unroll
        for (int o = 0; o < 8; o++) acc[o] = 0.f;
    }

    {
        const __half2* hv = (const __half2*)&v0;
        #pragma unroll
        for (int j = 0; j < 4; j++) {
            float2 p = __half22float2(hv[j]);
            acc[2*j]   += c0 * p.x;
            acc[2*j+1] += c0 * p.y;
        }
    }
    {
        const __half2* hv = (const __half2*)&v1;
        #pragma unroll
        for (int j = 0; j < 4; j++) {
            float2 p = __half22float2(hv[j]);
            acc[2*j]   += c1 * p.x;
            acc[2*j+1] += c1 * p.y;
        }
    }

    // combine the 4 lanes of each h-parity: {0,2,4,6} -> h=0, {1,3,5,7} -> h=1
    #pragma unroll
    for (int o = 0; o < 8; o++)
        acc[o] += __shfl_xor_sync(0xffffffffu, acc[o], 2);
    #pragma unroll
    for (int o = 0; o < 8; o++)
        acc[o] += __shfl_xor_sync(0xffffffffu, acc[o], 4);

    // single red.v2 from every lane: lane sub writes outputs
    //   (sub&1)*8 + (sub>>1)*2 .. +1   of the dst row (8 B each, 64 B total)
    {
        float* o = out + dst * OUT_C + (sub & 1) * 8 + s2 * 2;
        const float r0 = acc[s2 * 2];
        const float r1 = acc[s2 * 2 + 1];
        asm volatile("red.global.add.v2.f32 [%0], {%1, %2};"
                     :: "l"(o), "f"(r0), "f"(r1)
                     : "memory");
    }
}

extern "C" void kernel_launch(void* const* d_in, const int* in_sizes, int n_in,
                              void* d_out, int out_size)
{
    const float* x     = (const float*)d_in[0];
    const int*   ei    = (const int*)  d_in[1];
    const float* ea    = (const float*)d_in[2];
    const float* w_nn  = (const float*)d_in[3];
    const float* b_nn  = (const float*)d_in[4];
    const float* root  = (const float*)d_in[5];
    const float* bias  = (const float*)d_in[6];
    float* out = (float*)d_out;

    int echo = 0;
    if (out_size >= N_NODES * OUT_C + 2 * N_EDGES)                        echo |= 1;
    if (out_size >= N_NODES * OUT_C + 2 * N_EDGES + N_EDGES * EDGE_F)     echo |= 2;

    node_kernel<<<2048, 256>>>(x, ei, ea, w_nn, b_nn, root, bias, out, echo);
    edge_kernel<<<(N_EDGES * 8) / 256, 256>>>(ei, ea, out);
}

// round 8
// speedup vs baseline: 1.1593x; 1.1593x over previous
#include <cuda_runtime.h>
#include <cuda_fp16.h>

#define N_NODES 50000
#define N_EDGES 800000
#define IN_C    16
#define OUT_C   16
#define EDGE_F  8

// y table in fp16: per node 9 blocks (8 edge-feature + 1 bias) x 16 outputs,
// = 18 uint4, PADDED to 24 uint4 (384 B = 3 cache lines, 128B-aligned).
// slot j = f*2 + h  (f = feature block, h = output half, uint4 units)
#define YSTRIDE 24

__device__ __align__(128) uint4 g_yh[N_NODES * YSTRIDE];   // 19.2 MB

// ---------------------------------------------------------------------------
// Kernel A: per-node precompute only (fp16 y table + fused fp32 root init).
// Thread = (node, output-half h); x registers shared by both computations.
// ---------------------------------------------------------------------------
__global__ void node_kernel(const float* __restrict__ x,
                            const float* __restrict__ w_nn,
                            const float* __restrict__ b_nn,
                            const float* __restrict__ root,
                            const float* __restrict__ bias,
                            float* __restrict__ out)
{
    __shared__ float Wsh[9 * 256];      // [f][i*16+o], f==8 holds b_nn
    __shared__ float Rsh[256 + 16];     // root [i][o] + bias[o]

    for (int t = threadIdx.x; t < 2048; t += blockDim.x) Wsh[t] = w_nn[t];
    for (int t = threadIdx.x; t < 256;  t += blockDim.x) Wsh[2048 + t] = b_nn[t];
    for (int t = threadIdx.x; t < 256;  t += blockDim.x) Rsh[t] = root[t];
    for (int t = threadIdx.x; t < 16;   t += blockDim.x) Rsh[256 + t] = bias[t];
    __syncthreads();

    const int gsz  = gridDim.x * blockDim.x;
    const int tid0 = blockIdx.x * blockDim.x + threadIdx.x;

    for (int t = tid0; t < N_NODES * 2; t += gsz) {
        int n = t >> 1;
        int h = t & 1;                 // outputs h*8 .. h*8+7

        const float4* xr = (const float4*)(x + n * IN_C);
        float xv[16];
        #pragma unroll
        for (int ii = 0; ii < 4; ii++) {
            float4 xx = xr[ii];
            xv[4*ii+0] = xx.x; xv[4*ii+1] = xx.y; xv[4*ii+2] = xx.z; xv[4*ii+3] = xx.w;
        }

        // ---- 9 y-blocks (8 edge-feature + bias block) ----
        #pragma unroll
        for (int f = 0; f < 9; f++) {
            const float* wb = &Wsh[f * 256 + h * 8];
            float acc[8];
            #pragma unroll
            for (int o = 0; o < 8; o++) acc[o] = 0.f;
            #pragma unroll
            for (int i = 0; i < 16; i++) {
                float xi = xv[i];
                #pragma unroll
                for (int o = 0; o < 8; o++) acc[o] += xi * wb[i * 16 + o];
            }
            __half2 hv[4];
            #pragma unroll
            for (int j = 0; j < 4; j++)
                hv[j] = __floats2half2_rn(acc[2*j], acc[2*j+1]);
            g_yh[n * YSTRIDE + f * 2 + h] = *(const uint4*)hv;
        }

        // ---- fused root-term half: out[n][h*8+o] = bias + x[n] @ root ----
        {
            float racc[8];
            #pragma unroll
            for (int o = 0; o < 8; o++) racc[o] = Rsh[256 + h * 8 + o];
            #pragma unroll
            for (int i = 0; i < 16; i++) {
                float xi = xv[i];
                #pragma unroll
                for (int o = 0; o < 8; o++) racc[o] += xi * Rsh[i * 16 + h * 8 + o];
            }
            float4* od = (float4*)(out + n * OUT_C + h * 8);
            od[0] = make_float4(racc[0], racc[1], racc[2], racc[3]);
            od[1] = make_float4(racc[4], racc[5], racc[6], racc[7]);
        }
    }
}

// ---------------------------------------------------------------------------
// Kernel B: 4 lanes per edge (8 edges/warp) — the R5 engine, improved:
//   * single red.v4 instruction covers the full 64 B dst row (all 4 lanes
//     write disjoint quarters; lanes 2,3 use the shfl-duplicated halves)
//     -> 1 scatter wavefront/edge (was 2)
//   * echo streaming folded into the same threads (DRAM shadow of the
//     L1-bound gather): thread g < 2*N_EDGES does one ei-echo write and one
//     ea float4 copy.
// ---------------------------------------------------------------------------
__global__ void edge_kernel(const int*   __restrict__ ei,
                            const float* __restrict__ ea,
                            float* __restrict__ out,
                            int echo)
{
    const int g   = blockIdx.x * blockDim.x + threadIdx.x;
    const int e   = g >> 2;                 // edge id (grid exact: N_EDGES*4 thr)
    const int sub = g & 3;
    const int s2  = sub >> 1;               // f-parity this lane handles

    const int src = __ldg(&ei[e]);
    const int dst = __ldg(&ei[N_EDGES + e]);

    // edge coefficients: lane needs f = s2, s2+2, s2+4, s2+6
    const float4* ea4 = (const float4*)ea;
    const float4 a0 = ea4[2 * e];
    const float4 a1 = ea4[2 * e + 1];
    const float c0 = s2 ? a0.y : a0.x;
    const float c1 = s2 ? a0.w : a0.z;
    const float c2 = s2 ? a1.y : a1.x;
    const float c3 = s2 ? a1.w : a1.z;

    const uint4* yrow = g_yh + src * YSTRIDE;
    const uint4 v0 = yrow[sub];
    const uint4 v1 = yrow[sub + 4];
    const uint4 v2 = yrow[sub + 8];
    const uint4 v3 = yrow[sub + 12];

    float acc[8];
    if (sub < 2) {   // bias block slot 16+sub (f=8, h=sub), coefficient 1
        const uint4 vb = yrow[16 + sub];
        const __half2* hv = (const __half2*)&vb;
        #pragma unroll
        for (int j = 0; j < 4; j++) {
            float2 p = __half22float2(hv[j]);
            acc[2*j] = p.x; acc[2*j+1] = p.y;
        }
    } else {
        #pragma unroll
        for (int o = 0; o < 8; o++) acc[o] = 0.f;
    }

    #pragma unroll
    for (int b = 0; b < 4; b++) {
        const uint4  v  = (b == 0) ? v0 : (b == 1) ? v1 : (b == 2) ? v2 : v3;
        const float  cf = (b == 0) ? c0 : (b == 1) ? c1 : (b == 2) ? c2 : c3;
        const __half2* hv = (const __half2*)&v;
        #pragma unroll
        for (int j = 0; j < 4; j++) {
            float2 p = __half22float2(hv[j]);
            acc[2*j]   += cf * p.x;
            acc[2*j+1] += cf * p.y;
        }
    }

    // combine the two f-parities: lane pairs (0,2) and (1,3).
    // Afterwards lanes 0,2 both hold outputs 0..7; lanes 1,3 hold 8..15.
    #pragma unroll
    for (int o = 0; o < 8; o++)
        acc[o] += __shfl_xor_sync(0xffffffffu, acc[o], 2);

    // ONE red.v4 instruction covers the whole 64 B dst row:
    //   sub0 -> [0:4)=acc[0:4], sub2 -> [4:8)=acc[4:8],
    //   sub1 -> [8:12)=acc[0:4], sub3 -> [12:16)=acc[4:8]
    {
        float* o = out + dst * OUT_C + (sub & 1) * 8 + s2 * 4;
        float r0, r1, r2, r3;
        if (s2) { r0 = acc[4]; r1 = acc[5]; r2 = acc[6]; r3 = acc[7]; }
        else    { r0 = acc[0]; r1 = acc[1]; r2 = acc[2]; r3 = acc[3]; }
        asm volatile("red.global.add.v4.f32 [%0], {%1, %2, %3, %4};"
                     :: "l"(o), "f"(r0), "f"(r1), "f"(r2), "f"(r3)
                     : "memory");
    }

    // ---- echo streaming, riding the DRAM shadow ----
    if (g < 2 * N_EDGES) {
        if (echo & 1)
            out[N_NODES * OUT_C + g] = (float)__ldg(&ei[g]);
        if (echo & 2) {
            float4*       dst4 = (float4*)(out + N_NODES * OUT_C + 2 * N_EDGES);
            const float4* src4 = (const float4*)ea;
            dst4[g] = src4[g];
        }
    }
}

extern "C" void kernel_launch(void* const* d_in, const int* in_sizes, int n_in,
                              void* d_out, int out_size)
{
    const float* x     = (const float*)d_in[0];
    const int*   ei    = (const int*)  d_in[1];
    const float* ea    = (const float*)d_in[2];
    const float* w_nn  = (const float*)d_in[3];
    const float* b_nn  = (const float*)d_in[4];
    const float* root  = (const float*)d_in[5];
    const float* bias  = (const float*)d_in[6];
    float* out = (float*)d_out;

    int echo = 0;
    if (out_size >= N_NODES * OUT_C + 2 * N_EDGES)                        echo |= 1;
    if (out_size >= N_NODES * OUT_C + 2 * N_EDGES + N_EDGES * EDGE_F)     echo |= 2;

    node_kernel<<<1024, 256>>>(x, w_nn, b_nn, root, bias, out);
    edge_kernel<<<(N_EDGES * 4) / 256, 256>>>(ei, ea, out, echo);
}

// round 9
// speedup vs baseline: 1.2408x; 1.0703x over previous
#include <cuda_runtime.h>
#include <cuda_fp16.h>

#define N_NODES 50000
#define N_EDGES 800000
#define IN_C    16
#define OUT_C   16
#define EDGE_F  8

// y table in fp16: per node 9 blocks (8 edge-feature + 1 bias) x 16 outputs,
// = 18 uint4, PADDED to 24 uint4 (384 B = 3 cache lines, 128B-aligned).
// slot j = f*2 + h  (f = feature block, h = output half, uint4 units)
#define YSTRIDE 24

#define NGROUP (N_NODES / 4)     // 12500 node-groups of 4 (strided)

__device__ __align__(128) uint4 g_yh[N_NODES * YSTRIDE];   // 19.2 MB

// ---------------------------------------------------------------------------
// Kernel A: per-node precompute with 4-node register blocking.
// Thread = (node-group, output-half h); owns nodes grp + k*NGROUP, k=0..3.
// Each 8-float weight LDS is reused for 4 nodes (32 FMA) -> smem crossbar
// traffic cut 4x vs the per-node version.
// ---------------------------------------------------------------------------
__global__ void node_kernel(const float* __restrict__ x,
                            const float* __restrict__ w_nn,
                            const float* __restrict__ b_nn,
                            const float* __restrict__ root,
                            const float* __restrict__ bias,
                            float* __restrict__ out)
{
    __shared__ float Wsh[9 * 256];      // [f][i*16+o], f==8 holds b_nn
    __shared__ float Rsh[256 + 16];     // root [i][o] + bias[o]

    for (int t = threadIdx.x; t < 2048; t += blockDim.x) Wsh[t] = w_nn[t];
    for (int t = threadIdx.x; t < 256;  t += blockDim.x) Wsh[2048 + t] = b_nn[t];
    for (int t = threadIdx.x; t < 256;  t += blockDim.x) Rsh[t] = root[t];
    for (int t = threadIdx.x; t < 16;   t += blockDim.x) Rsh[256 + t] = bias[t];
    __syncthreads();

    const int gsz  = gridDim.x * blockDim.x;
    const int tid0 = blockIdx.x * blockDim.x + threadIdx.x;

    for (int t = tid0; t < NGROUP * 2; t += gsz) {
        const int grp = t >> 1;
        const int h   = t & 1;                 // outputs h*8 .. h*8+7

        // ---- load x for 4 strided nodes into registers ----
        float xv[4][16];
        #pragma unroll
        for (int k = 0; k < 4; k++) {
            const int n = grp + k * NGROUP;
            const float4* xr = (const float4*)(x + n * IN_C);
            #pragma unroll
            for (int ii = 0; ii < 4; ii++) {
                float4 xx = xr[ii];
                xv[k][4*ii+0] = xx.x; xv[k][4*ii+1] = xx.y;
                xv[k][4*ii+2] = xx.z; xv[k][4*ii+3] = xx.w;
            }
        }

        // ---- 9 y-blocks: weights LDS'd once, used for 4 nodes ----
        #pragma unroll
        for (int f = 0; f < 9; f++) {
            float acc[4][8];
            #pragma unroll
            for (int k = 0; k < 4; k++)
                #pragma unroll
                for (int o = 0; o < 8; o++) acc[k][o] = 0.f;

            const float* wb = &Wsh[f * 256 + h * 8];
            #pragma unroll
            for (int i = 0; i < 16; i++) {
                const float4 wlo = *(const float4*)(wb + i * 16);
                const float4 whi = *(const float4*)(wb + i * 16 + 4);
                const float w[8] = {wlo.x, wlo.y, wlo.z, wlo.w,
                                    whi.x, whi.y, whi.z, whi.w};
                #pragma unroll
                for (int k = 0; k < 4; k++) {
                    const float xi = xv[k][i];
                    #pragma unroll
                    for (int o = 0; o < 8; o++) acc[k][o] += xi * w[o];
                }
            }

            #pragma unroll
            for (int k = 0; k < 4; k++) {
                __half2 hv[4];
                #pragma unroll
                for (int j = 0; j < 4; j++)
                    hv[j] = __floats2half2_rn(acc[k][2*j], acc[k][2*j+1]);
                const int n = grp + k * NGROUP;
                g_yh[n * YSTRIDE + f * 2 + h] = *(const uint4*)hv;
            }
        }

        // ---- fused root-term halves for the 4 nodes ----
        {
            float racc[4][8];
            #pragma unroll
            for (int k = 0; k < 4; k++)
                #pragma unroll
                for (int o = 0; o < 8; o++) racc[k][o] = Rsh[256 + h * 8 + o];

            #pragma unroll
            for (int i = 0; i < 16; i++) {
                const float4 rlo = *(const float4*)&Rsh[i * 16 + h * 8];
                const float4 rhi = *(const float4*)&Rsh[i * 16 + h * 8 + 4];
                const float r[8] = {rlo.x, rlo.y, rlo.z, rlo.w,
                                    rhi.x, rhi.y, rhi.z, rhi.w};
                #pragma unroll
                for (int k = 0; k < 4; k++) {
                    const float xi = xv[k][i];
                    #pragma unroll
                    for (int o = 0; o < 8; o++) racc[k][o] += xi * r[o];
                }
            }

            #pragma unroll
            for (int k = 0; k < 4; k++) {
                const int n = grp + k * NGROUP;
                float4* od = (float4*)(out + n * OUT_C + h * 8);
                od[0] = make_float4(racc[k][0], racc[k][1], racc[k][2], racc[k][3]);
                od[1] = make_float4(racc[k][4], racc[k][5], racc[k][6], racc[k][7]);
            }
        }
    }
}

// ---------------------------------------------------------------------------
// Kernel B: 4 lanes per edge (8 edges/warp), single red.v4 scatter,
// echo streaming folded into the same threads (unchanged from R8 winner).
// ---------------------------------------------------------------------------
__global__ void edge_kernel(const int*   __restrict__ ei,
                            const float* __restrict__ ea,
                            float* __restrict__ out,
                            int echo)
{
    const int g   = blockIdx.x * blockDim.x + threadIdx.x;
    const int e   = g >> 2;                 // edge id (grid exact: N_EDGES*4 thr)
    const int sub = g & 3;
    const int s2  = sub >> 1;               // f-parity this lane handles

    const int src = __ldg(&ei[e]);
    const int dst = __ldg(&ei[N_EDGES + e]);

    // edge coefficients: lane needs f = s2, s2+2, s2+4, s2+6
    const float4* ea4 = (const float4*)ea;
    const float4 a0 = ea4[2 * e];
    const float4 a1 = ea4[2 * e + 1];
    const float c0 = s2 ? a0.y : a0.x;
    const float c1 = s2 ? a0.w : a0.z;
    const float c2 = s2 ? a1.y : a1.x;
    const float c3 = s2 ? a1.w : a1.z;

    const uint4* yrow = g_yh + src * YSTRIDE;
    const uint4 v0 = yrow[sub];
    const uint4 v1 = yrow[sub + 4];
    const uint4 v2 = yrow[sub + 8];
    const uint4 v3 = yrow[sub + 12];

    float acc[8];
    if (sub < 2) {   // bias block slot 16+sub (f=8, h=sub), coefficient 1
        const uint4 vb = yrow[16 + sub];
        const __half2* hv = (const __half2*)&vb;
        #pragma unroll
        for (int j = 0; j < 4; j++) {
            float2 p = __half22float2(hv[j]);
            acc[2*j] = p.x; acc[2*j+1] = p.y;
        }
    } else {
        #pragma unroll
        for (int o = 0; o < 8; o++) acc[o] = 0.f;
    }

    #pragma unroll
    for (int b = 0; b < 4; b++) {
        const uint4  v  = (b == 0) ? v0 : (b == 1) ? v1 : (b == 2) ? v2 : v3;
        const float  cf = (b == 0) ? c0 : (b == 1) ? c1 : (b == 2) ? c2 : c3;
        const __half2* hv = (const __half2*)&v;
        #pragma unroll
        for (int j = 0; j < 4; j++) {
            float2 p = __half22float2(hv[j]);
            acc[2*j]   += cf * p.x;
            acc[2*j+1] += cf * p.y;
        }
    }

    // combine the two f-parities: lane pairs (0,2) and (1,3).
    #pragma unroll
    for (int o = 0; o < 8; o++)
        acc[o] += __shfl_xor_sync(0xffffffffu, acc[o], 2);

    // ONE red.v4 instruction covers the whole 64 B dst row
    {
        float* o = out + dst * OUT_C + (sub & 1) * 8 + s2 * 4;
        float r0, r1, r2, r3;
        if (s2) { r0 = acc[4]; r1 = acc[5]; r2 = acc[6]; r3 = acc[7]; }
        else    { r0 = acc[0]; r1 = acc[1]; r2 = acc[2]; r3 = acc[3]; }
        asm volatile("red.global.add.v4.f32 [%0], {%1, %2, %3, %4};"
                     :: "l"(o), "f"(r0), "f"(r1), "f"(r2), "f"(r3)
                     : "memory");
    }

    // ---- echo streaming, riding the DRAM shadow ----
    if (g < 2 * N_EDGES) {
        if (echo & 1)
            out[N_NODES * OUT_C + g] = (float)__ldg(&ei[g]);
        if (echo & 2) {
            float4*       dst4 = (float4*)(out + N_NODES * OUT_C + 2 * N_EDGES);
            const float4* src4 = (const float4*)ea;
            dst4[g] = src4[g];
        }
    }
}

extern "C" void kernel_launch(void* const* d_in, const int* in_sizes, int n_in,
                              void* d_out, int out_size)
{
    const float* x     = (const float*)d_in[0];
    const int*   ei    = (const int*)  d_in[1];
    const float* ea    = (const float*)d_in[2];
    const float* w_nn  = (const float*)d_in[3];
    const float* b_nn  = (const float*)d_in[4];
    const float* root  = (const float*)d_in[5];
    const float* bias  = (const float*)d_in[6];
    float* out = (float*)d_out;

    int echo = 0;
    if (out_size >= N_NODES * OUT_C + 2 * N_EDGES)                        echo |= 1;
    if (out_size >= N_NODES * OUT_C + 2 * N_EDGES + N_EDGES * EDGE_F)     echo |= 2;

    // 25000 tasks (node-group x half); 196 blocks x 128 spreads across SMs
    node_kernel<<<196, 128>>>(x, w_nn, b_nn, root, bias, out);
    edge_kernel<<<(N_EDGES * 4) / 256, 256>>>(ei, ea, out, echo);
}